// round 6
// baseline (speedup 1.0000x reference)
#include <cuda_runtime.h>
#include <stdint.h>

// ---------------------------------------------------------------------------
// VanDerWallsSurface: scatter point features into a 128^3 voxel grid.
//  out[b,x,y,z] = [max f0, min f1, mean f2] over points whose sphere covers
//  the voxel (within the 5x5x5 neighborhood of round(coords)), else zeros.
//
// R6: dirty-line bitmap kills the 134MB full-Acc sweep.
//  R5 evidence: sweep was BW-bound at 5.4TB/s moving 235MB, but 96% of the
//  134MB Acc read was clean voxels.
//  R6: scatter also sets 1 dirty bit per touched 128B Acc line (131KB bitmap,
//  atomicOr). Kernel A fuses scatter (blocks first; latency-bound) with the
//  mandatory 100MB output zeroing (streaming __stcs so Acc stays L2-hot).
//  Kernel B visits only dirty lines: warp-broadcast bitmap word, dirty thread
//  reads its 128B Acc line, writes the 96B output block over the zeros, and
//  re-zeroes the line. Kernel C clears the bitmap (separate node: B's blocks
//  read the bitmap at arbitrary times).
//
//  - Order-preserving uint encodings make 0 the neutral element for all four
//    accumulators -> scratch is a zero-initialized static; B re-zeroes dirty
//    lines, C re-zeroes the bitmap: all-zero invariant across graph replays.
// ---------------------------------------------------------------------------

#define VOL        128
#define NB         4
#define NPTS       4096
#define NPOINTS    (NB * NPTS)            // 16384
#define KOFF       125                    // 5x5x5 offsets
#define NCAND      (NPOINTS * KOFF)       // 2,048,000 candidates
#define TOTAL_VOX  (NB * VOL * VOL * VOL) // 8,388,608
#define NLINES     (TOTAL_VOX / 8)        // 1,048,576 (8 Acc per 128B line)
#define NWORDS     (NLINES / 32)          // 32,768 bitmap words
#define TPB        256

#define SCAT_BLOCKS (NCAND / TPB)                       // 8,000
#define ZPT         4                                   // float4 stores/thread
#define ZERO_VEC    ((TOTAL_VOX * 3) / 4)               // 6,291,456 float4
#define ZERO_BLOCKS (ZERO_VEC / (TPB * ZPT))            // 6,144
#define FIN_BLOCKS  (NLINES / TPB)                      // 4,096

// Interleaved per-voxel accumulator: one 128B cache line covers all four
// fields of 8 z-adjacent voxels. All neutral elements are 0.
struct Acc {
    unsigned int maxk;  // max-key of f0
    unsigned int mink;  // ~min-key of f1 (min via max)
    unsigned int cnt;   // hit count
    float        sum;   // sum of f2
};
__device__ Acc          g_acc[TOTAL_VOX];  // zero-init; kept zero by k_finalize
__device__ unsigned int g_dirty[NWORDS];   // 1 bit per Acc line; cleared by k_clear

// Order-preserving float -> uint key. For any finite non-NaN f, fkey(f) > 0,
// so 0 is a valid "empty" sentinel for atomicMax accumulation.
__device__ __forceinline__ unsigned int fkey(float f) {
    unsigned int u = __float_as_uint(f);
    return (u & 0x80000000u) ? ~u : (u | 0x80000000u);
}
__device__ __forceinline__ float funkey(unsigned int k) {
    unsigned int u = (k & 0x80000000u) ? (k ^ 0x80000000u) : ~k;
    return __uint_as_float(u);
}

// Kernel A: blocks [0, SCAT_BLOCKS) run the scatter (latency-bound, issued
// first); remaining blocks stream 100MB of output zeros behind them with
// __stcs so the scatter's Acc lines stay resident in L2 for kernel B.
__global__ void __launch_bounds__(TPB) k_scatter_zero(
    const float4* __restrict__ cr,     // (B*N) x [cx, cy, cz, r]
    const float*  __restrict__ feat,   // (B*N) x 3
    float4*       __restrict__ out4)   // d_out viewed as float4
{
    int bid = blockIdx.x;
    if (bid >= SCAT_BLOCKS) {
        size_t base = ((size_t)(bid - SCAT_BLOCKS) * TPB + threadIdx.x) * ZPT;
        float4 z = make_float4(0.f, 0.f, 0.f, 0.f);
#pragma unroll
        for (int j = 0; j < ZPT; j++) __stcs(&out4[base + j], z);
        return;
    }

    int t  = bid * TPB + threadIdx.x;   // candidate id
    int k  = t % KOFF;
    int pn = t / KOFF;                  // linear point id

    float4 c = __ldg(cr + pn);  // 125 consecutive threads share -> L1 broadcast

    int ox = k / 25 - 2;
    int oy = (k / 5) % 5 - 2;
    int oz = k % 5 - 2;

    // jnp.round == round-half-to-even == rn conversions
    int vx = __float2int_rn(c.x) + ox;
    int vy = __float2int_rn(c.y) + oy;
    int vz = __float2int_rn(c.z) + oz;

    // Exact IEEE ops, left-to-right sum, matching the reference (no FMA
    // contraction that could flip sphere-boundary membership).
    float dx = __fsub_rn((float)vx, c.x);
    float dy = __fsub_rn((float)vy, c.y);
    float dz = __fsub_rn((float)vz, c.z);
    float d2 = __fadd_rn(__fadd_rn(__fmul_rn(dx, dx), __fmul_rn(dy, dy)),
                         __fmul_rn(dz, dz));

    float rr = __fdiv_rn(rintf(__fmul_rn(c.w, 1000.0f)), 1000.0f);
    float r2 = __fmul_rn(rr, rr);

    bool ok = (d2 <= r2)
            && ((unsigned)vx < VOL) && ((unsigned)vy < VOL) && ((unsigned)vz < VOL);
    if (!ok) return;

    unsigned e = (unsigned)((pn >> 12) * (VOL * VOL * VOL)
                            + ((vx * VOL + vy) * VOL + vz));

    const float* fp = feat + (size_t)pn * 3;
    float f0 = __ldg(fp + 0);
    float f1 = __ldg(fp + 1);
    float f2 = __ldg(fp + 2);

    Acc* a = &g_acc[e];
    atomicMax(&a->maxk, fkey(f0));
    atomicMax(&a->mink, ~fkey(f1));     // min via max of complemented key
    atomicAdd(&a->cnt, 1u);
    atomicAdd(&a->sum, f2);

    unsigned line = e >> 3;             // 8 Acc per 128B line
    atomicOr(&g_dirty[line >> 5], 1u << (line & 31u));
}

// Kernel B: one thread per Acc line. Warp loads one bitmap word (broadcast);
// clean threads exit. Dirty threads read their 128B Acc line, decode the 8
// voxels, overwrite the 96B output block (6 x float4), and zero the line.
__global__ void __launch_bounds__(TPB) k_finalize(float* __restrict__ out)
{
    unsigned L = blockIdx.x * TPB + threadIdx.x;      // line id
    unsigned w = __ldg(&g_dirty[L >> 5]);             // one word per warp
    if (((w >> (L & 31u)) & 1u) == 0u) return;

    uint4* accl = reinterpret_cast<uint4*>(g_acc) + (size_t)L * 8;

    float o[24];                                      // 8 voxels x 3 channels
#pragma unroll
    for (int j = 0; j < 8; j++) {
        uint4 a = accl[j];
        float v0 = 0.0f, v1 = 0.0f, v2 = 0.0f;
        if (a.z != 0u) {                              // cnt != 0
            v0 = funkey(a.x);
            v1 = funkey(~a.y);
            v2 = __fdiv_rn(__uint_as_float(a.w), (float)a.z);
        }
        o[j * 3 + 0] = v0;
        o[j * 3 + 1] = v1;
        o[j * 3 + 2] = v2;
    }

    uint4 z = make_uint4(0u, 0u, 0u, 0u);
#pragma unroll
    for (int j = 0; j < 8; j++) accl[j] = z;          // self-clean for next call

    // Output block for voxels [L*8, L*8+8): 96B at byte offset L*96 (16B-aligned).
    float4* ob = reinterpret_cast<float4*>(out + (size_t)L * 24);
#pragma unroll
    for (int j = 0; j < 6; j++)
        ob[j] = make_float4(o[j*4+0], o[j*4+1], o[j*4+2], o[j*4+3]);
}

// Kernel C: clear the bitmap (separate node: k_finalize's blocks read the
// bitmap at arbitrary times, so clearing can't be fused into it).
__global__ void k_clear()
{
    g_dirty[blockIdx.x * TPB + threadIdx.x] = 0u;
}

extern "C" void kernel_launch(void* const* d_in, const int* in_sizes, int n_in,
                              void* d_out, int out_size)
{
    const float4* cr   = (const float4*)d_in[0];  // coordinates_radii (B,N,4)
    const float*  feat = (const float*)d_in[1];   // features (B,N,3)
    float*        out  = (float*)d_out;           // (B,128,128,128,3) f32

    k_scatter_zero<<<SCAT_BLOCKS + ZERO_BLOCKS, TPB>>>(cr, feat, (float4*)out);
    k_finalize<<<FIN_BLOCKS, TPB>>>(out);
    k_clear<<<NWORDS / TPB, TPB>>>();
}

// round 7
// speedup vs baseline: 1.0764x; 1.0764x over previous
#include <cuda_runtime.h>
#include <stdint.h>

// ---------------------------------------------------------------------------
// VanDerWallsSurface: scatter point features into a 128^3 voxel grid.
//  out[b,x,y,z] = [max f0, min f1, mean f2] over points whose sphere covers
//  the voxel (within the 5x5x5 neighborhood of round(coords)), else zeros.
//
// R7: single-write output — zeroing fused INTO the finalize sweep.
//  R6 evidence: fused scatter+zero serialized by wave scheduling (36.9us at
//  1.9TB/s), output was written twice for dirty lines, and finalize+clear
//  added ~15us.
//  R7: Kernel A = scatter only (atomics into interleaved 16B Acc + dirty bit
//  per 128B Acc line). Kernel B = one thread per line: bitmap word is warp-
//  uniform; clean line -> write 96B zeros; dirty line -> read Acc line
//  (L2-hot from A), decode 8 voxels, write 96B values, re-zero the Acc line.
//  Each bitmap word belongs to exactly one warp, so the warp clears its own
//  word -> no third kernel. Output written exactly once (~100MB, the floor).
//
//  - Order-preserving uint encodings make 0 the neutral element for all four
//    accumulators -> scratch is a zero-initialized static; B re-zeroes dirty
//    lines and the bitmap: all-zero invariant across graph replays.
// ---------------------------------------------------------------------------

#define VOL        128
#define NB         4
#define NPTS       4096
#define NPOINTS    (NB * NPTS)            // 16384
#define KOFF       125                    // 5x5x5 offsets
#define NCAND      (NPOINTS * KOFF)       // 2,048,000 candidates
#define TOTAL_VOX  (NB * VOL * VOL * VOL) // 8,388,608
#define NLINES     (TOTAL_VOX / 8)        // 1,048,576 (8 Acc per 128B line)
#define NWORDS     (NLINES / 32)          // 32,768 bitmap words
#define TPB        256

#define SCAT_BLOCKS  (NCAND / TPB)        // 8,000
#define SWEEP_BLOCKS (NLINES / TPB)       // 4,096

// Interleaved per-voxel accumulator: one 128B cache line covers all four
// fields of 8 z-adjacent voxels. All neutral elements are 0.
struct Acc {
    unsigned int maxk;  // max-key of f0
    unsigned int mink;  // ~min-key of f1 (min via max)
    unsigned int cnt;   // hit count
    float        sum;   // sum of f2
};
__device__ Acc          g_acc[TOTAL_VOX];  // zero-init; kept zero by k_sweep
__device__ unsigned int g_dirty[NWORDS];   // 1 bit per Acc line; cleared by k_sweep

// Order-preserving float -> uint key. For any finite non-NaN f, fkey(f) > 0,
// so 0 is a valid "empty" sentinel for atomicMax accumulation.
__device__ __forceinline__ unsigned int fkey(float f) {
    unsigned int u = __float_as_uint(f);
    return (u & 0x80000000u) ? ~u : (u | 0x80000000u);
}
__device__ __forceinline__ float funkey(unsigned int k) {
    unsigned int u = (k & 0x80000000u) ? (k ^ 0x80000000u) : ~k;
    return __uint_as_float(u);
}

// Kernel A: one thread per (point, offset) candidate; hits do 4 atomics into
// the voxel's interleaved Acc plus one dirty-bit atomicOr per touched line.
__global__ void __launch_bounds__(TPB) k_scatter(
    const float4* __restrict__ cr,     // (B*N) x [cx, cy, cz, r]
    const float*  __restrict__ feat)   // (B*N) x 3
{
    int t  = blockIdx.x * TPB + threadIdx.x;   // candidate id
    int k  = t % KOFF;
    int pn = t / KOFF;                         // linear point id

    float4 c = __ldg(cr + pn);  // 125 consecutive threads share -> L1 broadcast

    int ox = k / 25 - 2;
    int oy = (k / 5) % 5 - 2;
    int oz = k % 5 - 2;

    // jnp.round == round-half-to-even == rn conversions
    int vx = __float2int_rn(c.x) + ox;
    int vy = __float2int_rn(c.y) + oy;
    int vz = __float2int_rn(c.z) + oz;

    // Exact IEEE ops, left-to-right sum, matching the reference (no FMA
    // contraction that could flip sphere-boundary membership).
    float dx = __fsub_rn((float)vx, c.x);
    float dy = __fsub_rn((float)vy, c.y);
    float dz = __fsub_rn((float)vz, c.z);
    float d2 = __fadd_rn(__fadd_rn(__fmul_rn(dx, dx), __fmul_rn(dy, dy)),
                         __fmul_rn(dz, dz));

    float rr = __fdiv_rn(rintf(__fmul_rn(c.w, 1000.0f)), 1000.0f);
    float r2 = __fmul_rn(rr, rr);

    bool ok = (d2 <= r2)
            && ((unsigned)vx < VOL) && ((unsigned)vy < VOL) && ((unsigned)vz < VOL);
    if (!ok) return;

    unsigned e = (unsigned)((pn >> 12) * (VOL * VOL * VOL)
                            + ((vx * VOL + vy) * VOL + vz));

    const float* fp = feat + (size_t)pn * 3;
    float f0 = __ldg(fp + 0);
    float f1 = __ldg(fp + 1);
    float f2 = __ldg(fp + 2);

    Acc* a = &g_acc[e];
    atomicMax(&a->maxk, fkey(f0));
    atomicMax(&a->mink, ~fkey(f1));     // min via max of complemented key
    atomicAdd(&a->cnt, 1u);
    atomicAdd(&a->sum, f2);

    unsigned line = e >> 3;             // 8 Acc per 128B line
    atomicOr(&g_dirty[line >> 5], 1u << (line & 31u));
}

// Kernel B: one thread per Acc line; writes the output exactly once.
// Bitmap word is warp-uniform (32 consecutive lines = 1 warp = 1 word).
// Clean line: stream 96B of zeros. Dirty line: read the 128B Acc line
// (L2-hot from kernel A), decode 8 voxels, write 96B, re-zero the Acc line.
// The owning warp clears its bitmap word afterwards (exclusive ownership).
__global__ void __launch_bounds__(TPB) k_sweep(float* __restrict__ out)
{
    unsigned L    = blockIdx.x * TPB + threadIdx.x;   // line id
    unsigned widx = L >> 5;
    unsigned w    = g_dirty[widx];                    // warp-uniform load

    // Output block for voxels [L*8, L*8+8): 96B at float offset L*24.
    float4* ob = reinterpret_cast<float4*>(out + (size_t)L * 24);

    if (((w >> (L & 31u)) & 1u) == 0u) {
        float4 z = make_float4(0.f, 0.f, 0.f, 0.f);
#pragma unroll
        for (int j = 0; j < 6; j++) __stcs(&ob[j], z);
    } else {
        uint4* accl = reinterpret_cast<uint4*>(g_acc) + (size_t)L * 8;

        float o[24];                                  // 8 voxels x 3 channels
#pragma unroll
        for (int j = 0; j < 8; j++) {
            uint4 a = accl[j];
            float v0 = 0.0f, v1 = 0.0f, v2 = 0.0f;
            if (a.z != 0u) {                          // cnt != 0
                v0 = funkey(a.x);
                v1 = funkey(~a.y);
                v2 = __fdiv_rn(__uint_as_float(a.w), (float)a.z);
            }
            o[j * 3 + 0] = v0;
            o[j * 3 + 1] = v1;
            o[j * 3 + 2] = v2;
        }

        uint4 z4 = make_uint4(0u, 0u, 0u, 0u);
#pragma unroll
        for (int j = 0; j < 8; j++) accl[j] = z4;     // self-clean for next call

#pragma unroll
        for (int j = 0; j < 6; j++)
            __stcs(&ob[j], make_float4(o[j*4+0], o[j*4+1], o[j*4+2], o[j*4+3]));
    }

    // Clear the bitmap word. Exactly one warp owns each word; every lane has
    // already consumed w from its register, so no intra-warp hazard. Skip the
    // store when already zero (the common case) to avoid 131KB of dead writes.
    if ((L & 31u) == 0u && w != 0u) g_dirty[widx] = 0u;
}

extern "C" void kernel_launch(void* const* d_in, const int* in_sizes, int n_in,
                              void* d_out, int out_size)
{
    const float4* cr   = (const float4*)d_in[0];  // coordinates_radii (B,N,4)
    const float*  feat = (const float*)d_in[1];   // features (B,N,3)
    float*        out  = (float*)d_out;           // (B,128,128,128,3) f32

    k_scatter<<<SCAT_BLOCKS, TPB>>>(cr, feat);
    k_sweep<<<SWEEP_BLOCKS, TPB>>>(out);
}

// round 8
// speedup vs baseline: 1.3185x; 1.2250x over previous
#include <cuda_runtime.h>
#include <stdint.h>

// ---------------------------------------------------------------------------
// VanDerWallsSurface: scatter point features into a 128^3 voxel grid.
//  out[b,x,y,z] = [max f0, min f1, mean f2] over points whose sphere covers
//  the voxel (within the 5x5x5 neighborhood of round(coords)), else zeros.
//
// R8: R5's execution shape + R7's traffic reduction.
//  R7 evidence: per-LINE sweep (1M threads, 6 dependent STG.128, regs=44)
//  collapsed to 1.87TB/s / occ=49% — latency/issue-bound, not BW-bound.
//  R5 evidence: per-VOXEL sweep (8.4M threads, scalar stores) ran 5.4TB/s.
//  R8: per-voxel sweep, bitmap-gated. One block (256 threads) = 256 voxels =
//  32 lines = exactly ONE bitmap word -> broadcast load, and the block clears
//  its own word after __syncthreads(). Clean voxel: 12B of zeros. Dirty
//  voxel: 16B Acc read (L2-hot from scatter), decode, 12B out, 16B Acc clean.
//  Output written exactly once; total ~152MB vs R5's 235MB.
//
//  - Order-preserving uint encodings make 0 the neutral element for all four
//    accumulators -> scratch is a zero-initialized static; the sweep re-zeroes
//    dirty Acc entries and its bitmap word: all-zero across graph replays.
// ---------------------------------------------------------------------------

#define VOL        128
#define NB         4
#define NPTS       4096
#define NPOINTS    (NB * NPTS)            // 16384
#define KOFF       125                    // 5x5x5 offsets
#define NCAND      (NPOINTS * KOFF)       // 2,048,000 candidates
#define TOTAL_VOX  (NB * VOL * VOL * VOL) // 8,388,608
#define NLINES     (TOTAL_VOX / 8)        // 1,048,576 (8 Acc per 128B line)
#define NWORDS     (NLINES / 32)          // 32,768 bitmap words
#define TPB        256

#define SCAT_BLOCKS  (NCAND / TPB)        // 8,000
#define SWEEP_BLOCKS (TOTAL_VOX / TPB)    // 32,768  (== NWORDS: 1 word/block)

// Interleaved per-voxel accumulator: one 128B cache line covers all four
// fields of 8 z-adjacent voxels. All neutral elements are 0.
struct Acc {
    unsigned int maxk;  // max-key of f0
    unsigned int mink;  // ~min-key of f1 (min via max)
    unsigned int cnt;   // hit count
    float        sum;   // sum of f2
};
__device__ Acc          g_acc[TOTAL_VOX];  // zero-init; kept zero by k_sweep
__device__ unsigned int g_dirty[NWORDS];   // 1 bit per Acc line; cleared by k_sweep

// Order-preserving float -> uint key. For any finite non-NaN f, fkey(f) > 0,
// so 0 is a valid "empty" sentinel for atomicMax accumulation.
__device__ __forceinline__ unsigned int fkey(float f) {
    unsigned int u = __float_as_uint(f);
    return (u & 0x80000000u) ? ~u : (u | 0x80000000u);
}
__device__ __forceinline__ float funkey(unsigned int k) {
    unsigned int u = (k & 0x80000000u) ? (k ^ 0x80000000u) : ~k;
    return __uint_as_float(u);
}

// Kernel A: one thread per (point, offset) candidate; hits do 4 atomics into
// the voxel's interleaved Acc plus one dirty-bit atomicOr per touched line.
__global__ void __launch_bounds__(TPB) k_scatter(
    const float4* __restrict__ cr,     // (B*N) x [cx, cy, cz, r]
    const float*  __restrict__ feat)   // (B*N) x 3
{
    int t  = blockIdx.x * TPB + threadIdx.x;   // candidate id
    int k  = t % KOFF;
    int pn = t / KOFF;                         // linear point id

    float4 c = __ldg(cr + pn);  // 125 consecutive threads share -> L1 broadcast

    int ox = k / 25 - 2;
    int oy = (k / 5) % 5 - 2;
    int oz = k % 5 - 2;

    // jnp.round == round-half-to-even == rn conversions
    int vx = __float2int_rn(c.x) + ox;
    int vy = __float2int_rn(c.y) + oy;
    int vz = __float2int_rn(c.z) + oz;

    // Exact IEEE ops, left-to-right sum, matching the reference (no FMA
    // contraction that could flip sphere-boundary membership).
    float dx = __fsub_rn((float)vx, c.x);
    float dy = __fsub_rn((float)vy, c.y);
    float dz = __fsub_rn((float)vz, c.z);
    float d2 = __fadd_rn(__fadd_rn(__fmul_rn(dx, dx), __fmul_rn(dy, dy)),
                         __fmul_rn(dz, dz));

    float rr = __fdiv_rn(rintf(__fmul_rn(c.w, 1000.0f)), 1000.0f);
    float r2 = __fmul_rn(rr, rr);

    bool ok = (d2 <= r2)
            && ((unsigned)vx < VOL) && ((unsigned)vy < VOL) && ((unsigned)vz < VOL);
    if (!ok) return;

    unsigned e = (unsigned)((pn >> 12) * (VOL * VOL * VOL)
                            + ((vx * VOL + vy) * VOL + vz));

    const float* fp = feat + (size_t)pn * 3;
    float f0 = __ldg(fp + 0);
    float f1 = __ldg(fp + 1);
    float f2 = __ldg(fp + 2);

    Acc* a = &g_acc[e];
    atomicMax(&a->maxk, fkey(f0));
    atomicMax(&a->mink, ~fkey(f1));     // min via max of complemented key
    atomicAdd(&a->cnt, 1u);
    atomicAdd(&a->sum, f2);

    unsigned line = e >> 3;             // 8 Acc per 128B line
    atomicOr(&g_dirty[line >> 5], 1u << (line & 31u));
}

// Kernel B: one thread per voxel (max MLP, scalar stores — the shape that hit
// 5.4TB/s in R5), gated by the dirty bitmap. Block b covers voxels
// [b*256, b*256+256) = lines [b*32, b*32+32) = bitmap word b exactly.
__global__ void __launch_bounds__(TPB) k_sweep(float* __restrict__ out)
{
    unsigned b = blockIdx.x;
    unsigned e = b * TPB + threadIdx.x;        // voxel id
    unsigned w = g_dirty[b];                   // block-uniform broadcast load

    size_t o = (size_t)e * 3;                  // 12B/thread, coalesced
    unsigned line_in_word = (e >> 3) & 31u;

    if (((w >> line_in_word) & 1u) == 0u) {    // clean line (common case)
        __stcs(out + o + 0, 0.0f);
        __stcs(out + o + 1, 0.0f);
        __stcs(out + o + 2, 0.0f);
    } else {
        uint4* ap = reinterpret_cast<uint4*>(g_acc) + e;
        uint4 a = *ap;
        float v0 = 0.0f, v1 = 0.0f, v2 = 0.0f;
        if (a.z != 0u) {                       // cnt != 0
            v0 = funkey(a.x);
            v1 = funkey(~a.y);
            v2 = __fdiv_rn(__uint_as_float(a.w), (float)a.z);
            *ap = make_uint4(0u, 0u, 0u, 0u);  // self-clean for next call
        }
        __stcs(out + o + 0, v0);
        __stcs(out + o + 1, v1);
        __stcs(out + o + 2, v2);
    }

    // Clear this block's bitmap word. All threads of the block have already
    // consumed w; the barrier orders the reads before the single clear.
    if (w != 0u) {
        __syncthreads();
        if (threadIdx.x == 0) g_dirty[b] = 0u;
    }
}

extern "C" void kernel_launch(void* const* d_in, const int* in_sizes, int n_in,
                              void* d_out, int out_size)
{
    const float4* cr   = (const float4*)d_in[0];  // coordinates_radii (B,N,4)
    const float*  feat = (const float*)d_in[1];   // features (B,N,3)
    float*        out  = (float*)d_out;           // (B,128,128,128,3) f32

    k_scatter<<<SCAT_BLOCKS, TPB>>>(cr, feat);
    k_sweep<<<SWEEP_BLOCKS, TPB>>>(out);
}

// round 9
// speedup vs baseline: 1.3391x; 1.0156x over previous
#include <cuda_runtime.h>
#include <stdint.h>

// ---------------------------------------------------------------------------
// VanDerWallsSurface: scatter point features into a 128^3 voxel grid.
//  out[b,x,y,z] = [max f0, min f1, mean f2] over points whose sphere covers
//  the voxel (within the 5x5x5 neighborhood of round(coords)), else zeros.
//
// R9: dense float4 output stores via smem staging.
//  R8 evidence: sweep not BW-bound (DRAM=20.8%, 1.65TB/s). Each thread's 3
//  stride-3 scalar stores cost 3 L1tex wavefronts apiece (9/warp, 72/block)
//  where dense stores need 24/block -> L1tex replay was the limiter.
//  R9: per-voxel decode into a 3KB smem tile (stride-3 smem writes are
//  conflict-free, gcd(3,32)=1), one __syncthreads(), then 192 threads emit
//  the block's output as dense float4 stores. Dirty-path Acc reads stay
//  lane-dense. Bitmap word is per-block and cleared after the barrier.
//
//  - Order-preserving uint encodings make 0 the neutral element for all four
//    accumulators -> scratch is a zero-initialized static; the sweep re-zeroes
//    dirty Acc entries and its bitmap word: all-zero across graph replays.
// ---------------------------------------------------------------------------

#define VOL        128
#define NB         4
#define NPTS       4096
#define NPOINTS    (NB * NPTS)            // 16384
#define KOFF       125                    // 5x5x5 offsets
#define NCAND      (NPOINTS * KOFF)       // 2,048,000 candidates
#define TOTAL_VOX  (NB * VOL * VOL * VOL) // 8,388,608
#define NLINES     (TOTAL_VOX / 8)        // 1,048,576 (8 Acc per 128B line)
#define NWORDS     (NLINES / 32)          // 32,768 bitmap words
#define TPB        256

#define SCAT_BLOCKS  (NCAND / TPB)        // 8,000
#define SWEEP_BLOCKS (TOTAL_VOX / TPB)    // 32,768  (== NWORDS: 1 word/block)

// Interleaved per-voxel accumulator: one 128B cache line covers all four
// fields of 8 z-adjacent voxels. All neutral elements are 0.
struct Acc {
    unsigned int maxk;  // max-key of f0
    unsigned int mink;  // ~min-key of f1 (min via max)
    unsigned int cnt;   // hit count
    float        sum;   // sum of f2
};
__device__ Acc          g_acc[TOTAL_VOX];  // zero-init; kept zero by k_sweep
__device__ unsigned int g_dirty[NWORDS];   // 1 bit per Acc line; cleared by k_sweep

// Order-preserving float -> uint key. For any finite non-NaN f, fkey(f) > 0,
// so 0 is a valid "empty" sentinel for atomicMax accumulation.
__device__ __forceinline__ unsigned int fkey(float f) {
    unsigned int u = __float_as_uint(f);
    return (u & 0x80000000u) ? ~u : (u | 0x80000000u);
}
__device__ __forceinline__ float funkey(unsigned int k) {
    unsigned int u = (k & 0x80000000u) ? (k ^ 0x80000000u) : ~k;
    return __uint_as_float(u);
}

// Kernel A: one thread per (point, offset) candidate; hits do 4 atomics into
// the voxel's interleaved Acc plus one dirty-bit atomicOr per touched line.
__global__ void __launch_bounds__(TPB) k_scatter(
    const float4* __restrict__ cr,     // (B*N) x [cx, cy, cz, r]
    const float*  __restrict__ feat)   // (B*N) x 3
{
    int t  = blockIdx.x * TPB + threadIdx.x;   // candidate id
    int k  = t % KOFF;
    int pn = t / KOFF;                         // linear point id

    float4 c = __ldg(cr + pn);  // 125 consecutive threads share -> L1 broadcast

    int ox = k / 25 - 2;
    int oy = (k / 5) % 5 - 2;
    int oz = k % 5 - 2;

    // jnp.round == round-half-to-even == rn conversions
    int vx = __float2int_rn(c.x) + ox;
    int vy = __float2int_rn(c.y) + oy;
    int vz = __float2int_rn(c.z) + oz;

    // Exact IEEE ops, left-to-right sum, matching the reference (no FMA
    // contraction that could flip sphere-boundary membership).
    float dx = __fsub_rn((float)vx, c.x);
    float dy = __fsub_rn((float)vy, c.y);
    float dz = __fsub_rn((float)vz, c.z);
    float d2 = __fadd_rn(__fadd_rn(__fmul_rn(dx, dx), __fmul_rn(dy, dy)),
                         __fmul_rn(dz, dz));

    float rr = __fdiv_rn(rintf(__fmul_rn(c.w, 1000.0f)), 1000.0f);
    float r2 = __fmul_rn(rr, rr);

    bool ok = (d2 <= r2)
            && ((unsigned)vx < VOL) && ((unsigned)vy < VOL) && ((unsigned)vz < VOL);
    if (!ok) return;

    unsigned e = (unsigned)((pn >> 12) * (VOL * VOL * VOL)
                            + ((vx * VOL + vy) * VOL + vz));

    const float* fp = feat + (size_t)pn * 3;
    float f0 = __ldg(fp + 0);
    float f1 = __ldg(fp + 1);
    float f2 = __ldg(fp + 2);

    Acc* a = &g_acc[e];
    atomicMax(&a->maxk, fkey(f0));
    atomicMax(&a->mink, ~fkey(f1));     // min via max of complemented key
    atomicAdd(&a->cnt, 1u);
    atomicAdd(&a->sum, f2);

    unsigned line = e >> 3;             // 8 Acc per 128B line
    atomicOr(&g_dirty[line >> 5], 1u << (line & 31u));
}

// Kernel B: one thread per voxel, bitmap-gated, smem-staged dense output.
// Block b covers voxels [b*256, b*256+256) = lines [b*32, b*32+32) = bitmap
// word b exactly. Decode into a 3KB smem tile (stride-3 writes: conflict-free,
// gcd(3,32)=1); then 192 threads stream the tile as dense float4 stores.
__global__ void __launch_bounds__(TPB) k_sweep(float* __restrict__ out)
{
    __shared__ __align__(16) float s[TPB * 3];     // 3KB output tile

    unsigned b = blockIdx.x;
    unsigned e = b * TPB + threadIdx.x;            // voxel id
    unsigned w = g_dirty[b];                       // block-uniform broadcast

    float v0 = 0.0f, v1 = 0.0f, v2 = 0.0f;
    unsigned line_in_word = (threadIdx.x >> 3) & 31u;   // == (e>>3)&31
    if ((w >> line_in_word) & 1u) {                // dirty line
        uint4* ap = reinterpret_cast<uint4*>(g_acc) + e; // lane-dense read
        uint4 a = *ap;
        if (a.z != 0u) {                           // cnt != 0
            v0 = funkey(a.x);
            v1 = funkey(~a.y);
            v2 = __fdiv_rn(__uint_as_float(a.w), (float)a.z);
            *ap = make_uint4(0u, 0u, 0u, 0u);      // self-clean for next call
        }
    }
    s[threadIdx.x * 3 + 0] = v0;
    s[threadIdx.x * 3 + 1] = v1;
    s[threadIdx.x * 3 + 2] = v2;
    __syncthreads();

    // Emit the block's contiguous 3KB output region as 192 dense float4.
    if (threadIdx.x < 192) {
        float4 val = reinterpret_cast<const float4*>(s)[threadIdx.x];
        __stcs(reinterpret_cast<float4*>(out) + (size_t)b * 192 + threadIdx.x, val);
    }

    // Clear this block's bitmap word (all threads consumed w before the
    // barrier; exclusive per-block ownership).
    if (w != 0u && threadIdx.x == 0) g_dirty[b] = 0u;
}

extern "C" void kernel_launch(void* const* d_in, const int* in_sizes, int n_in,
                              void* d_out, int out_size)
{
    const float4* cr   = (const float4*)d_in[0];  // coordinates_radii (B,N,4)
    const float*  feat = (const float*)d_in[1];   // features (B,N,3)
    float*        out  = (float*)d_out;           // (B,128,128,128,3) f32

    k_scatter<<<SCAT_BLOCKS, TPB>>>(cr, feat);
    k_sweep<<<SWEEP_BLOCKS, TPB>>>(out);
}